// round 13
// baseline (speedup 1.0000x reference)
#include <cuda_runtime.h>
#include <cstdint>

#define A_TOT 49056
#define AHALF (A_TOT/2)          // 24528 key-pair words per (b,c) plane
#define BATCH 32
#define NFG 7
#define KTOP 200
#define NBC (BATCH*NFG)          // 224
#define NBIN 2048
#define HSHIFT 21                // bin = key32 >> 21
#define NCHUNK 767               // ceil(AHALF/32) chunks of 32 words (64 anchors)
#define NCHUNKP 768
#define CANDMAX 4096
#define SORTMAX 2048
#define NMS_THR_F 0.45f
#define LOW_SCORE_F 0.01f

// ---------------- scratch (device globals) -----------------------------------
__device__ unsigned g_k16[(size_t)NBC * AHALF];        // packed (key16 lo | key16 hi)
__device__ unsigned short g_wmax[NBC * NCHUNKP];       // per-chunk max key16
__device__ unsigned g_hist[NBC * NBIN];
__device__ unsigned g_cand[NBC * CANDMAX];             // anchor indices
__device__ int g_ccnt[NBC];
__device__ float g_ks[NBC * KTOP];                     // kept scores (sorted desc)
__device__ int   g_km[NBC * KTOP];                     // kept anchors
__device__ int   g_kcnt[NBC];

// ---- exact softmax (candidates only; bit-exact final ordering) --------------
__device__ __forceinline__ void softmax8(const float4 l0, const float4 l1, float* fg7) {
    float x[8] = {l0.x, l0.y, l0.z, l0.w, l1.x, l1.y, l1.z, l1.w};
    float mx = x[0];
#pragma unroll
    for (int i = 1; i < 8; i++) mx = fmaxf(mx, x[i]);
    float e[8]; float sum = 0.f;
#pragma unroll
    for (int i = 0; i < 8; i++) { e[i] = expf(x[i] - mx); sum += e[i]; }
    float inv = 1.0f / sum;
#pragma unroll
    for (int c = 0; c < NFG; c++) fg7[c] = e[c + 1] * inv;
}

// ---- polynomial exp2: no MUFU, rel err <= ~1e-5 -----------------------------
__device__ __forceinline__ float fexp2(float t) {
    t = fminf(fmaxf(t, -60.f), 60.f);
    float r = rintf(t);
    float f = t - r;                                   // [-0.5, 0.5]
    float u = f * 0.6931471805599453f;
    float p = 1.0f + u * (1.0f + u * (0.5f + u * (0.16666667f
              + u * (0.041666667f + u * 0.0083333333f))));
    return p * __int_as_float(((int)r + 127) << 23);
}
// no max-subtraction: ratio mathematically identical, error absorbed by margin
__device__ __forceinline__ void softmax8_fast(const float4 l0, const float4 l1, float* fg7) {
    float x[8] = {l0.x, l0.y, l0.z, l0.w, l1.x, l1.y, l1.z, l1.w};
    float e[8]; float sum = 0.f;
#pragma unroll
    for (int i = 0; i < 8; i++) { e[i] = fexp2(x[i] * 1.4426950408889634f); sum += e[i]; }
    float inv = __fdividef(1.0f, sum);
#pragma unroll
    for (int c = 0; c < NFG; c++) fg7[c] = e[c + 1] * inv;
}

__device__ __forceinline__ float4 decode_box(float4 d, float4 db) {
    float w  = db.z - db.x,  h  = db.w - db.y;
    float cx = db.x + 0.5f * w, cy = db.y + 0.5f * h;
    float pcx = d.x / 10.0f * w + cx;
    float pcy = d.y / 10.0f * h + cy;
    float pw  = expf(d.z / 5.0f) * w;
    float ph  = expf(d.w / 5.0f) * h;
    return make_float4(
        fminf(fmaxf(pcx - 0.5f * pw, 0.f), 1.f),
        fminf(fmaxf(pcy - 0.5f * ph, 0.f), 1.f),
        fminf(fmaxf(pcx + 0.5f * pw, 0.f), 1.f),
        fminf(fmaxf(pcy + 0.5f * ph, 0.f), 1.f));
}

// ---------------- K0: zero histograms ----------------------------------------
__global__ void k_zero() {
    int i = blockIdx.x * 1024 + threadIdx.x;
    if (i < NBC * NBIN / 4) ((uint4*)g_hist)[i] = make_uint4(0, 0, 0, 0);
}

// ---------------- K1: fast softmax -> keys + chunk maxima + histogram --------
__global__ void k_prep(const float* __restrict__ logits) {
    int b = blockIdx.x >> 4;                   // 16 chunks per image
    int chunk = blockIdx.x & 15;
    int tid = threadIdx.x;
    int lane = tid & 31;
    __shared__ unsigned hist[NFG * (NBIN / 2)]; // u16-packed halves, 28 KB
    for (int i = tid; i < NFG * (NBIN / 2); i += 256) hist[i] = 0;
    __syncthreads();

    int wbase = chunk * 1536 + tid;
#pragma unroll
    for (int k = 0; k < 6; k++) {
        int w = wbase + k * 256;
        bool act = w < AHALF;
        float f0[NFG], f1[NFG];
        if (act) {
            size_t aidx = (size_t)b * A_TOT + 2 * w;
            const float4* lp = (const float4*)logits + aidx * 2;
            softmax8_fast(lp[0], lp[1], f0);
            softmax8_fast(lp[2], lp[3], f1);
        }
        int cid = w >> 5;
#pragma unroll
        for (int c = 0; c < NFG; c++) {
            unsigned k0 = 0, k1 = 0;
            if (act) {
                k0 = __float_as_uint(f0[c]);
                k1 = __float_as_uint(f1[c]);
                g_k16[(size_t)(b * NFG + c) * AHALF + w] = (k0 >> 16) | ((k1 >> 16) << 16);
            }
            unsigned v16 = (k0 > k1 ? k0 : k1) >> 16;
            unsigned wm = __reduce_max_sync(0xffffffffu, v16);
            if (lane == 0)
                g_wmax[(b * NFG + c) * NCHUNKP + cid] = (unsigned short)wm;
            // warp-aggregated histogram: one atomic per distinct bin per warp
            unsigned bb0 = act ? (k0 >> HSHIFT) : (4096u + lane);
            unsigned g0 = __match_any_sync(0xffffffffu, bb0);
            if (act && lane == (unsigned)(__ffs(g0) - 1))
                atomicAdd(&hist[c * (NBIN / 2) + (bb0 >> 1)],
                          (unsigned)__popc(g0) << ((bb0 & 1) * 16));
            unsigned bb1 = act ? (k1 >> HSHIFT) : (4096u + lane);
            unsigned g1 = __match_any_sync(0xffffffffu, bb1);
            if (act && lane == (unsigned)(__ffs(g1) - 1))
                atomicAdd(&hist[c * (NBIN / 2) + (bb1 >> 1)],
                          (unsigned)__popc(g1) << ((bb1 & 1) * 16));
        }
    }
    __syncthreads();
    for (int i = tid; i < NFG * (NBIN / 2); i += 256) {
        unsigned v = hist[i];
        if (!v) continue;
        int c = i / (NBIN / 2), bp = i % (NBIN / 2);
        unsigned lo = v & 0xffffu, hi = v >> 16;
        unsigned* gh = &g_hist[(b * NFG + c) * NBIN + bp * 2];
        if (lo) atomicAdd(gh, lo);
        if (hi) atomicAdd(gh + 1, hi);
    }
}

// ---------------- K2: per-plane threshold + sparse candidate compaction ------
__global__ void k_sel() {
    int bc = blockIdx.x;                        // one block per (b,c) plane
    int tid = threadIdx.x;                      // 256 threads
    int lane = tid & 31, wid = tid >> 5;

    __shared__ int csum[256];
    __shared__ int suf[257];
    __shared__ unsigned sh_thr;
    if (tid == 0) sh_thr = 0;                   // safe default: select all
    const unsigned* h = g_hist + bc * NBIN;
    unsigned loc[8]; int s = 0;
    int base = tid * 8;
#pragma unroll
    for (int i = 0; i < 8; i++) { loc[i] = h[base + i]; s += (int)loc[i]; }
    csum[tid] = s;
    __syncthreads();
    if (tid == 0) {
        int acc = 0; suf[256] = 0;
        for (int t = 255; t >= 0; t--) { acc += csum[t]; suf[t] = acc; }
    }
    __syncthreads();
    int above = suf[tid + 1];
    if (above < KTOP && above + s >= KTOP) {
        int cum = above;
        for (int i = 7; i >= 0; i--) {
            cum += (int)loc[i];
            if (cum >= KTOP) {
                float edge = __uint_as_float((unsigned)(base + i) << HSHIFT);
                sh_thr = __float_as_uint(edge * 0.9995f) >> 16;  // superset margin
                break;
            }
        }
    }
    __shared__ int hits[NCHUNKP];
    __shared__ int hcnt, ccnt;
    if (tid == 0) { hcnt = 0; ccnt = 0; }
    __syncthreads();
    unsigned thr = sh_thr;

    const unsigned short* wmax = g_wmax + bc * NCHUNKP;
#pragma unroll
    for (int it = 0; it < 3; it++) {
        int cid = tid + it * 256;
        bool pass = (cid < NCHUNK) && ((unsigned)wmax[cid] >= thr);
        unsigned m = __ballot_sync(0xffffffffu, pass);
        if (m) {
            int bse = 0;
            if (lane == __ffs(m) - 1) bse = atomicAdd(&hcnt, __popc(m));
            bse = __shfl_sync(0xffffffffu, bse, __ffs(m) - 1);
            if (pass) hits[bse + __popc(m & ((1u << lane) - 1u))] = cid;
        }
    }
    __syncthreads();

    __shared__ int cand[CANDMAX];               // 16 KB
    int nh = hcnt;
    const unsigned* plane = g_k16 + (size_t)bc * AHALF;
    for (int hh = wid; hh < nh; hh += 8) {
        int cid = hits[hh];
        int w = cid * 32 + lane;
        unsigned v = (w < AHALF) ? plane[w] : 0u;
        bool p0 = (w < AHALF) && ((v & 0xffffu) >= thr);
        bool p1 = (w < AHALF) && ((v >> 16) >= thr);
        unsigned m0 = __ballot_sync(0xffffffffu, p0);
        unsigned m1 = __ballot_sync(0xffffffffu, p1);
        int c0 = __popc(m0), c1 = __popc(m1);
        if (c0 + c1) {
            int bse = 0;
            if (lane == 0) bse = atomicAdd(&ccnt, c0 + c1);
            bse = __shfl_sync(0xffffffffu, bse, 0);
            unsigned below = (1u << lane) - 1u;
            if (p0) { int p = bse + __popc(m0 & below);      if (p < CANDMAX) cand[p] = 2 * w; }
            if (p1) { int p = bse + c0 + __popc(m1 & below); if (p < CANDMAX) cand[p] = 2 * w + 1; }
        }
    }
    __syncthreads();

    int n = ccnt < CANDMAX ? ccnt : CANDMAX;
    for (int i = tid; i < n; i += 256) g_cand[bc * CANDMAX + i] = (unsigned)cand[i];
    if (tid == 0) g_ccnt[bc] = n;
}

// ---------------- K3: exact keys, hist-select, small sort, NMS, compact ------
__global__ __launch_bounds__(512) void k_nms(const float* __restrict__ logits,
                                             const float* __restrict__ deltas,
                                             const float* __restrict__ dbox) {
    int bc = blockIdx.x;
    int b = bc / NFG, c = bc % NFG;
    int tid = threadIdx.x;                      // 512 threads
    int lane = tid & 31, wrp = tid >> 5;

    __shared__ unsigned long long sortbuf[SORTMAX];   // 16 KB
    __shared__ union U {
        struct { unsigned key32[CANDMAX]; unsigned hist[NBIN]; } a;   // 24 KB
        struct {
            float x0[KTOP], y0[KTOP], x1[KTOP], y1[KTOP], ar[KTOP], ss[KTOP];
            int an[KTOP];
            unsigned mask[KTOP * 7];
        } b2;                                                          // 11.2 KB
    } u;
    __shared__ int wsum[16];
    __shared__ int wsuf[17];
    __shared__ int sh_T, selcnt;
    __shared__ unsigned remw[7];
    __shared__ int woff[8];

    int n = g_ccnt[bc]; if (n > CANDMAX) n = CANDMAX;

    for (int i = tid; i < NBIN; i += 512) u.a.hist[i] = 0;
    if (tid == 0) { selcnt = 0; sh_T = 0; }     // T=0 default: select all
    __syncthreads();

    // exact keys + exact-key histogram
    for (int i = tid; i < n; i += 512) {
        int a = (int)g_cand[bc * CANDMAX + i];
        const float4* lp = (const float4*)logits + ((size_t)b * A_TOT + a) * 2;
        float fg[NFG];
        softmax8(lp[0], lp[1], fg);             // EXACT
        unsigned key = __float_as_uint(fg[c]);
        u.a.key32[i] = key;
        atomicAdd(&u.a.hist[key >> HSHIFT], 1u);
    }
    __syncthreads();

    // find bin T: largest bin with suffix-count >= KTOP (two-level shfl scan)
    int loc[4]; int s = 0; int base = tid * 4;
#pragma unroll
    for (int i2 = 0; i2 < 4; i2++) { loc[i2] = (int)u.a.hist[base + i2]; s += loc[i2]; }
    int v = s;
#pragma unroll
    for (int d = 1; d < 32; d <<= 1) {
        int t2 = __shfl_down_sync(0xffffffffu, v, d);
        if (lane + d < 32) v += t2;
    }
    if (lane == 0) wsum[wrp] = v;
    __syncthreads();
    if (tid == 0) {
        int acc = 0; wsuf[16] = 0;
        for (int t = 15; t >= 0; t--) { acc += wsum[t]; wsuf[t] = acc; }
    }
    __syncthreads();
    int above = (v - s) + wsuf[wrp + 1];
    if (above < KTOP && above + s >= KTOP) {
        int cum = above;
        for (int i2 = 3; i2 >= 0; i2--) {
            cum += loc[i2];
            if (cum >= KTOP) { sh_T = base + i2; break; }
        }
    }
    __syncthreads();
    unsigned T = (unsigned)sh_T;

    // compact candidates with bin >= T into sortbuf (composite key)
    int niter = (n + 511) / 512;
    for (int it = 0; it < niter; it++) {
        int i = it * 512 + tid;
        bool act = (i < n) && ((u.a.key32[i] >> HSHIFT) >= T);
        unsigned m = __ballot_sync(0xffffffffu, act);
        if (m) {
            int ldr = __ffs(m) - 1;
            int bse = 0;
            if (lane == ldr) bse = atomicAdd(&selcnt, __popc(m));
            bse = __shfl_sync(0xffffffffu, bse, ldr);
            if (act) {
                int p = bse + __popc(m & ((1u << lane) - 1u));
                if (p < SORTMAX)
                    sortbuf[p] = ((unsigned long long)u.a.key32[i] << 32)
                               | (unsigned)(A_TOT - (int)g_cand[bc * CANDMAX + i]);
            }
        }
    }
    __syncthreads();
    int cnt = selcnt; if (cnt > SORTMAX) cnt = SORTMAX;
    int npad = 256; while (npad < cnt) npad <<= 1;
    for (int i = cnt + tid; i < npad; i += 512) sortbuf[i] = 0ULL;
    __syncthreads();

    // bitonic sort (small: typically npad == 256)
    for (int k = 2; k <= npad; k <<= 1)
        for (int j = k >> 1; j > 0; j >>= 1) {
            for (int t = tid; t < npad; t += 512) {
                int l = t ^ j;
                if (l > t) {
                    bool desc = ((t & k) == 0);
                    unsigned long long va = sortbuf[t], vb = sortbuf[l];
                    if (desc ? (va < vb) : (va > vb)) { sortbuf[t] = vb; sortbuf[l] = va; }
                }
            }
            __syncthreads();
        }
    // u.a is dead from here on -> union switch to u.b2

    if (tid < KTOP) {
        unsigned long long vv = sortbuf[tid];
        unsigned key = (unsigned)(vv >> 32);
        int a = A_TOT - (int)(vv & 0xffffffffu);
        if (vv == 0ULL) a = 0;                  // padding entry: score 0, never kept
        float4 d  = ((const float4*)deltas)[(size_t)b * A_TOT + a];
        float4 db = ((const float4*)dbox)[a];
        float4 bx = decode_box(d, db);
        u.b2.x0[tid] = bx.x; u.b2.y0[tid] = bx.y; u.b2.x1[tid] = bx.z; u.b2.y1[tid] = bx.w;
        u.b2.ar[tid] = (bx.z - bx.x) * (bx.w - bx.y);
        u.b2.ss[tid] = __uint_as_float(key); u.b2.an[tid] = a;
    }
    for (int i = tid; i < KTOP * 7; i += 512) u.b2.mask[i] = 0;
    __syncthreads();

    for (int p = tid; p < KTOP * KTOP; p += 512) {
        int i = p / KTOP, j = p - i * KTOP;
        if (j > i) {
            float xl = fmaxf(u.b2.x0[i], u.b2.x0[j]);
            float yt = fmaxf(u.b2.y0[i], u.b2.y0[j]);
            float xr = fminf(u.b2.x1[i], u.b2.x1[j]);
            float yb = fminf(u.b2.y1[i], u.b2.y1[j]);
            float inter = fmaxf(xr - xl, 0.f) * fmaxf(yb - yt, 0.f);
            float iou = inter / (u.b2.ar[i] + u.b2.ar[j] - inter);  // NaN -> false
            if (iou > NMS_THR_F) atomicOr(&u.b2.mask[i * 7 + (j >> 5)], 1u << (j & 31));
        }
    }
    __syncthreads();

    // greedy scan with suppressed-row skipping (warp 0)
    if (tid < 32) {
        unsigned rem = 0;
        if (tid < 7)
            for (int j = 0; j < 32; j++) {
                int jj = tid * 32 + j;
                if (jj >= KTOP || !(u.b2.ss[jj] > LOW_SCORE_F)) rem |= 1u << j;
            }
        int i = 0;
        while (i < KTOP) {
            int w = i >> 5;
            unsigned rw = __shfl_sync(0xffffffffu, rem, w);
            unsigned below = (i & 31) ? ((1u << (i & 31)) - 1u) : 0u;
            unsigned free = ~(rw | below);
            if (!free) { i = (w + 1) << 5; continue; }
            i = (w << 5) + (__ffs(free) - 1);
            if (i >= KTOP) break;
            if (tid < 7) rem |= u.b2.mask[i * 7 + tid];
            i++;
        }
        if (tid < 7) remw[tid] = rem;
    }
    __syncthreads();

    if (tid == 0) {
        int s2 = 0;
        for (int w = 0; w < 7; w++) {
            unsigned valid = (w < 6) ? 0xffffffffu : 0xffu;   // 200 = 6*32+8
            woff[w] = s2;
            s2 += __popc(~remw[w] & valid);
        }
        g_kcnt[bc] = s2;
    }
    __syncthreads();
    if (tid < KTOP) {
        int w = tid >> 5;
        bool keep = !((remw[w] >> (tid & 31)) & 1u);
        if (keep) {
            int pos = woff[w] + __popc(~remw[w] & ((1u << (tid & 31)) - 1u));
            g_ks[bc * KTOP + pos] = u.b2.ss[tid];
            g_km[bc * KTOP + pos] = u.b2.an[tid];
        }
    }
}

// ---------------- K4: per-image rank-merge + decode + emit -------------------
__global__ void k_out(const float* __restrict__ deltas,
                      const float* __restrict__ dbox,
                      float* __restrict__ out) {
    int b = blockIdx.x;
    int tid = threadIdx.x;                      // 1024 threads
    __shared__ float skey[NFG * KTOP];
    __shared__ int   san[NFG * KTOP];
    __shared__ int   scnt[NFG];
    __shared__ int   total;
    if (tid < NFG) scnt[tid] = g_kcnt[b * NFG + tid];
    for (int i = tid; i < NFG * KTOP; i += 1024) {
        skey[i] = g_ks[b * NFG * KTOP + i];
        san[i]  = g_km[b * NFG * KTOP + i];
    }
    if (tid == 0) {
        int t = 0;
        for (int c = 0; c < NFG; c++) t += g_kcnt[b * NFG + c];
        total = t < KTOP ? t : KTOP;
    }
    __syncthreads();
    for (int i = total + tid; i < KTOP; i += 1024) {
        ((float4*)out)[b * KTOP + i] = make_float4(0.f, 0.f, 0.f, 0.f);
        out[BATCH * KTOP * 4 + b * KTOP + i] = 0.f;
        out[BATCH * KTOP * 5 + b * KTOP + i] = 0.f;
    }
    for (int i = tid; i < NFG * KTOP; i += 1024) {
        int c = i / KTOP, p = i - c * KTOP;
        if (p < scnt[c]) {
            float k = skey[i];
            int rank = p;
#pragma unroll
            for (int c2 = 0; c2 < NFG; c2++) {
                if (c2 == c) continue;
                int lo = 0, hi = scnt[c2];
                while (lo < hi) {
                    int mid = (lo + hi) >> 1;
                    float v = skey[c2 * KTOP + mid];
                    bool prec = (v > k) || (v == k && c2 < c);
                    if (prec) lo = mid + 1; else hi = mid;
                }
                rank += lo;
            }
            if (rank < KTOP) {
                int a = san[i];
                float4 d  = ((const float4*)deltas)[(size_t)b * A_TOT + a];
                float4 db = ((const float4*)dbox)[a];
                float4 bx = decode_box(d, db);
                ((float4*)out)[b * KTOP + rank] = bx;
                out[BATCH * KTOP * 4 + b * KTOP + rank] = k;
                out[BATCH * KTOP * 5 + b * KTOP + rank] = (float)(c + 1);
            }
        }
    }
}

// -----------------------------------------------------------------------------
extern "C" void kernel_launch(void* const* d_in, const int* in_sizes, int n_in,
                              void* d_out, int out_size) {
    const float* logits = nullptr;
    const float* deltas = nullptr;
    const float* dbox   = nullptr;
    for (int i = 0; i < n_in; i++) {
        if      (in_sizes[i] == BATCH * A_TOT * 8) logits = (const float*)d_in[i];
        else if (in_sizes[i] == BATCH * A_TOT * 4) deltas = (const float*)d_in[i];
        else if (in_sizes[i] == A_TOT * 4)         dbox   = (const float*)d_in[i];
    }
    float* out = (float*)d_out;

    k_zero<<<(NBC * NBIN / 4 + 1023) / 1024, 1024>>>();
    k_prep<<<BATCH * 16, 256>>>(logits);
    k_sel<<<NBC, 256>>>();
    k_nms<<<NBC, 512>>>(logits, deltas, dbox);
    k_out<<<BATCH, 1024>>>(deltas, dbox, out);
}

// round 14
// speedup vs baseline: 1.0775x; 1.0775x over previous
#include <cuda_runtime.h>
#include <cstdint>

#define A_TOT 49056
#define AHALF (A_TOT/2)          // 24528 key-pair words per (b,c) plane
#define BATCH 32
#define NFG 7
#define KTOP 200
#define NBC (BATCH*NFG)          // 224
#define NBIN 2048
#define HSHIFT 21                // bin = key32 >> 21 == key16 >> 5
#define NCHUNK 767               // ceil(AHALF/32) chunks of 32 words (64 anchors)
#define NCHUNKP 768
#define CANDMAX 4096
#define SORTMAX 2048
#define NMS_THR_F 0.45f
#define LOW_SCORE_F 0.01f

// ---------------- scratch (device globals) -----------------------------------
__device__ unsigned g_k16[(size_t)NBC * AHALF];        // packed (key16 lo | key16 hi)
__device__ unsigned short g_wmax[NBC * NCHUNKP];       // per-chunk max key16
__device__ unsigned g_hist[NBC * NBIN];
__device__ unsigned g_cand[NBC * CANDMAX];             // anchor indices
__device__ int g_ccnt[NBC];
__device__ float g_ks[NBC * KTOP];                     // kept scores (sorted desc)
__device__ int   g_km[NBC * KTOP];                     // kept anchors
__device__ int   g_kcnt[NBC];

// ---- exact softmax (candidates only; bit-exact final ordering) --------------
__device__ __forceinline__ void softmax8(const float4 l0, const float4 l1, float* fg7) {
    float x[8] = {l0.x, l0.y, l0.z, l0.w, l1.x, l1.y, l1.z, l1.w};
    float mx = x[0];
#pragma unroll
    for (int i = 1; i < 8; i++) mx = fmaxf(mx, x[i]);
    float e[8]; float sum = 0.f;
#pragma unroll
    for (int i = 0; i < 8; i++) { e[i] = expf(x[i] - mx); sum += e[i]; }
    float inv = 1.0f / sum;
#pragma unroll
    for (int c = 0; c < NFG; c++) fg7[c] = e[c + 1] * inv;
}

// ---- polynomial exp2: no MUFU, rel err <= ~1e-5 -----------------------------
__device__ __forceinline__ float fexp2(float t) {
    t = fminf(fmaxf(t, -60.f), 60.f);
    float r = rintf(t);
    float f = t - r;                                   // [-0.5, 0.5]
    float u = f * 0.6931471805599453f;
    float p = 1.0f + u * (1.0f + u * (0.5f + u * (0.16666667f
              + u * (0.041666667f + u * 0.0083333333f))));
    return p * __int_as_float(((int)r + 127) << 23);
}
__device__ __forceinline__ void softmax8_fast(const float4 l0, const float4 l1, float* fg7) {
    float x[8] = {l0.x, l0.y, l0.z, l0.w, l1.x, l1.y, l1.z, l1.w};
    float e[8]; float sum = 0.f;
#pragma unroll
    for (int i = 0; i < 8; i++) { e[i] = fexp2(x[i] * 1.4426950408889634f); sum += e[i]; }
    float inv = __fdividef(1.0f, sum);
#pragma unroll
    for (int c = 0; c < NFG; c++) fg7[c] = e[c + 1] * inv;
}

__device__ __forceinline__ float4 decode_box(float4 d, float4 db) {
    float w  = db.z - db.x,  h  = db.w - db.y;
    float cx = db.x + 0.5f * w, cy = db.y + 0.5f * h;
    float pcx = d.x / 10.0f * w + cx;
    float pcy = d.y / 10.0f * h + cy;
    float pw  = expf(d.z / 5.0f) * w;
    float ph  = expf(d.w / 5.0f) * h;
    return make_float4(
        fminf(fmaxf(pcx - 0.5f * pw, 0.f), 1.f),
        fminf(fmaxf(pcy - 0.5f * ph, 0.f), 1.f),
        fminf(fmaxf(pcx + 0.5f * pw, 0.f), 1.f),
        fminf(fmaxf(pcy + 0.5f * ph, 0.f), 1.f));
}

// ---------------- K0: zero histograms ----------------------------------------
__global__ void k_zero() {
    int i = blockIdx.x * 1024 + threadIdx.x;
    if (i < NBC * NBIN / 4) ((uint4*)g_hist)[i] = make_uint4(0, 0, 0, 0);
}

// ---------------- K1: fast softmax -> keys + chunk maxima + histogram --------
__global__ void k_prep(const float* __restrict__ logits) {
    int b = blockIdx.x >> 4;                   // 16 chunks per image
    int chunk = blockIdx.x & 15;
    int tid = threadIdx.x;
    int lane = tid & 31;
    __shared__ unsigned hist[NFG * (NBIN / 2)]; // u16-packed halves, 28 KB
    for (int i = tid; i < NFG * (NBIN / 2); i += 256) hist[i] = 0;
    __syncthreads();

    int wbase = chunk * 1536 + tid;
#pragma unroll
    for (int k = 0; k < 6; k++) {
        int w = wbase + k * 256;
        bool act = w < AHALF;
        float f0[NFG], f1[NFG];
        if (act) {
            size_t aidx = (size_t)b * A_TOT + 2 * w;
            const float4* lp = (const float4*)logits + aidx * 2;
            softmax8_fast(lp[0], lp[1], f0);
            softmax8_fast(lp[2], lp[3], f1);
        }
        int cid = w >> 5;
#pragma unroll
        for (int c = 0; c < NFG; c++) {
            unsigned k0 = 0, k1 = 0;
            if (act) {
                k0 = __float_as_uint(f0[c]);
                k1 = __float_as_uint(f1[c]);
                g_k16[(size_t)(b * NFG + c) * AHALF + w] = (k0 >> 16) | ((k1 >> 16) << 16);
            }
            unsigned v16 = (k0 > k1 ? k0 : k1) >> 16;
            unsigned wm = __reduce_max_sync(0xffffffffu, v16);
            if (lane == 0)
                g_wmax[(b * NFG + c) * NCHUNKP + cid] = (unsigned short)wm;
            unsigned bb0 = act ? (k0 >> HSHIFT) : (4096u + lane);
            unsigned g0 = __match_any_sync(0xffffffffu, bb0);
            if (act && lane == (unsigned)(__ffs(g0) - 1))
                atomicAdd(&hist[c * (NBIN / 2) + (bb0 >> 1)],
                          (unsigned)__popc(g0) << ((bb0 & 1) * 16));
            unsigned bb1 = act ? (k1 >> HSHIFT) : (4096u + lane);
            unsigned g1 = __match_any_sync(0xffffffffu, bb1);
            if (act && lane == (unsigned)(__ffs(g1) - 1))
                atomicAdd(&hist[c * (NBIN / 2) + (bb1 >> 1)],
                          (unsigned)__popc(g1) << ((bb1 & 1) * 16));
        }
    }
    __syncthreads();
    for (int i = tid; i < NFG * (NBIN / 2); i += 256) {
        unsigned v = hist[i];
        if (!v) continue;
        int c = i / (NBIN / 2), bp = i % (NBIN / 2);
        unsigned lo = v & 0xffffu, hi = v >> 16;
        unsigned* gh = &g_hist[(b * NFG + c) * NBIN + bp * 2];
        if (lo) atomicAdd(gh, lo);
        if (hi) atomicAdd(gh + 1, hi);
    }
}

// -------- K2: per-plane FINE (key16) threshold + sparse compaction -----------
__global__ void k_sel() {
    int bc = blockIdx.x;                        // one block per (b,c) plane
    int tid = threadIdx.x;                      // 256 threads
    int lane = tid & 31, wid = tid >> 5;

    // --- Phase A: coarse crossing bin B + count strictly above it -----------
    __shared__ int csum[256];
    __shared__ int suf[257];
    __shared__ int sh_B, sh_above;
    if (tid == 0) { sh_B = 0; sh_above = 0; }
    const unsigned* h = g_hist + bc * NBIN;
    unsigned loc[8]; int s = 0;
    int base = tid * 8;
#pragma unroll
    for (int i = 0; i < 8; i++) { loc[i] = h[base + i]; s += (int)loc[i]; }
    csum[tid] = s;
    __syncthreads();
    if (tid == 0) {
        int acc = 0; suf[256] = 0;
        for (int t = 255; t >= 0; t--) { acc += csum[t]; suf[t] = acc; }
    }
    __syncthreads();
    int above0 = suf[tid + 1];
    if (above0 < KTOP && above0 + s >= KTOP) {
        int cum = above0;
        for (int i = 7; i >= 0; i--) {
            cum += (int)loc[i];
            if (cum >= KTOP) { sh_B = base + i; sh_above = cum - (int)loc[i]; break; }
        }
    }
    __shared__ int hits[NCHUNKP];
    __shared__ int hcnt, ccnt;
    __shared__ int subh[32];
    __shared__ unsigned sh_thr16;
    if (tid == 0) { hcnt = 0; ccnt = 0; }
    if (tid < 32) subh[tid] = 0;
    __syncthreads();
    int B = sh_B, above = sh_above;
    int ht = (B << 5) - 2; if (ht < 0) ht = 0;  // hit thr = final-thr lower bound
    unsigned hthr = (unsigned)ht;

    // --- Phase B: chunks that can contain candidates -------------------------
    const unsigned short* wmax = g_wmax + bc * NCHUNKP;
#pragma unroll
    for (int it = 0; it < 3; it++) {
        int cid = tid + it * 256;
        bool pass = (cid < NCHUNK) && ((unsigned)wmax[cid] >= hthr);
        unsigned m = __ballot_sync(0xffffffffu, pass);
        if (m) {
            int bse = 0;
            if (lane == __ffs(m) - 1) bse = atomicAdd(&hcnt, __popc(m));
            bse = __shfl_sync(0xffffffffu, bse, __ffs(m) - 1);
            if (pass) hits[bse + __popc(m & ((1u << lane) - 1u))] = cid;
        }
    }
    __syncthreads();
    int nh = hcnt;
    const unsigned* plane = g_k16 + (size_t)bc * AHALF;

    // --- Phase C1: 32-bin sub-histogram of keys inside coarse bin B ----------
    for (int hh = wid; hh < nh; hh += 8) {
        int w = hits[hh] * 32 + lane;
        if (w < AHALF) {
            unsigned v = plane[w];
            unsigned k0 = v & 0xffffu, k1 = v >> 16;
            if ((int)(k0 >> 5) == B) atomicAdd(&subh[k0 & 31], 1);
            if ((int)(k1 >> 5) == B) atomicAdd(&subh[k1 & 31], 1);
        }
    }
    __syncthreads();
    if (tid == 0) {
        int acc = above, T2 = 0;
        for (int s2 = 31; s2 >= 0; s2--) {
            acc += subh[s2];
            if (acc >= KTOP) { T2 = s2; break; }
        }
        int t16 = B * 32 + T2 - 2;              // 2-ulp margin covers approx err
        sh_thr16 = (unsigned)(t16 > 0 ? t16 : 0);
    }
    __syncthreads();
    unsigned thr = sh_thr16;

    // --- Phase C2: select candidates with key16 >= thr -----------------------
    __shared__ int cand[CANDMAX];               // 16 KB
    for (int hh = wid; hh < nh; hh += 8) {
        int w = hits[hh] * 32 + lane;
        unsigned v = (w < AHALF) ? plane[w] : 0u;
        bool p0 = (w < AHALF) && ((v & 0xffffu) >= thr);
        bool p1 = (w < AHALF) && ((v >> 16) >= thr);
        unsigned m0 = __ballot_sync(0xffffffffu, p0);
        unsigned m1 = __ballot_sync(0xffffffffu, p1);
        int c0 = __popc(m0), c1 = __popc(m1);
        if (c0 + c1) {
            int bse = 0;
            if (lane == 0) bse = atomicAdd(&ccnt, c0 + c1);
            bse = __shfl_sync(0xffffffffu, bse, 0);
            unsigned below = (1u << lane) - 1u;
            if (p0) { int p = bse + __popc(m0 & below);      if (p < CANDMAX) cand[p] = 2 * w; }
            if (p1) { int p = bse + c0 + __popc(m1 & below); if (p < CANDMAX) cand[p] = 2 * w + 1; }
        }
    }
    __syncthreads();

    int n = ccnt < CANDMAX ? ccnt : CANDMAX;
    for (int i = tid; i < n; i += 256) g_cand[bc * CANDMAX + i] = (unsigned)cand[i];
    if (tid == 0) g_ccnt[bc] = n;
}

// ---------------- K3: exact keys, small sort, NMS, compact -------------------
__global__ __launch_bounds__(512) void k_nms(const float* __restrict__ logits,
                                             const float* __restrict__ deltas,
                                             const float* __restrict__ dbox) {
    int bc = blockIdx.x;
    int b = bc / NFG, c = bc % NFG;
    int tid = threadIdx.x;                      // 512 threads
    int lane = tid & 31;

    __shared__ unsigned long long sortbuf[SORTMAX];   // 16 KB
    __shared__ float x0[KTOP], y0[KTOP], x1[KTOP], y1[KTOP], ar[KTOP], ss[KTOP];
    __shared__ int   an[KTOP];
    __shared__ uint4 mask4[KTOP * 2];           // mask rows, stride 8 words (6.4 KB)
    unsigned* mask = (unsigned*)mask4;
    __shared__ unsigned remw[7];
    __shared__ int woff[8];

    int n = g_ccnt[bc]; if (n > SORTMAX) n = SORTMAX;

    // exact composite keys straight into sortbuf (n is small now: ~200-400)
    for (int i = tid; i < n; i += 512) {
        int a = (int)g_cand[bc * CANDMAX + i];
        const float4* lp = (const float4*)logits + ((size_t)b * A_TOT + a) * 2;
        float fg[NFG];
        softmax8(lp[0], lp[1], fg);             // EXACT
        sortbuf[i] = ((unsigned long long)__float_as_uint(fg[c]) << 32)
                   | (unsigned)(A_TOT - a);
    }
    int npad = 256; while (npad < n) npad <<= 1;
    for (int i = n + tid; i < npad; i += 512) sortbuf[i] = 0ULL;
    __syncthreads();

    // bitonic sort (typically npad == 256)
    for (int k = 2; k <= npad; k <<= 1)
        for (int j = k >> 1; j > 0; j >>= 1) {
            for (int t = tid; t < npad; t += 512) {
                int l = t ^ j;
                if (l > t) {
                    bool desc = ((t & k) == 0);
                    unsigned long long va = sortbuf[t], vb = sortbuf[l];
                    if (desc ? (va < vb) : (va > vb)) { sortbuf[t] = vb; sortbuf[l] = va; }
                }
            }
            __syncthreads();
        }

    if (tid < KTOP) {
        unsigned long long vv = sortbuf[tid];
        unsigned key = (unsigned)(vv >> 32);
        int a = A_TOT - (int)(vv & 0xffffffffu);
        if (vv == 0ULL) a = 0;                  // padding: score 0, never kept
        float4 d  = ((const float4*)deltas)[(size_t)b * A_TOT + a];
        float4 db = ((const float4*)dbox)[a];
        float4 bx = decode_box(d, db);
        x0[tid] = bx.x; y0[tid] = bx.y; x1[tid] = bx.z; y1[tid] = bx.w;
        ar[tid] = (bx.z - bx.x) * (bx.w - bx.y);
        ss[tid] = __uint_as_float(key); an[tid] = a;
    }
    for (int i = tid; i < KTOP * 8; i += 512) mask[i] = 0;
    __syncthreads();

    for (int p = tid; p < KTOP * KTOP; p += 512) {
        int i = p / KTOP, j = p - i * KTOP;
        if (j > i) {
            float xl = fmaxf(x0[i], x0[j]);
            float yt = fmaxf(y0[i], y0[j]);
            float xr = fminf(x1[i], x1[j]);
            float yb = fminf(y1[i], y1[j]);
            float inter = fmaxf(xr - xl, 0.f) * fmaxf(yb - yt, 0.f);
            float iou = inter / (ar[i] + ar[j] - inter);  // NaN -> false
            if (iou > NMS_THR_F) atomicOr(&mask[i * 8 + (j >> 5)], 1u << (j & 31));
        }
    }
    __syncthreads();

    // greedy: init words by warp-0 ballots, then single-lane register scan
    if (tid < 32) {
        unsigned bw[7];
#pragma unroll
        for (int w = 0; w < 7; w++) {
            int jj = w * 32 + lane;
            bool bad = (jj >= KTOP) || !(ss[jj] > LOW_SCORE_F);
            bw[w] = __ballot_sync(0xffffffffu, bad);
        }
        if (lane == 0) {
            unsigned r0 = bw[0], r1 = bw[1], r2 = bw[2], r3 = bw[3],
                     r4 = bw[4], r5 = bw[5], r6 = bw[6];
#define PROC_ROW(ib) { \
    uint4 ma = mask4[(ib) * 2], mb = mask4[(ib) * 2 + 1]; \
    r0 |= ma.x; r1 |= ma.y; r2 |= ma.z; r3 |= ma.w; \
    r4 |= mb.x; r5 |= mb.y; r6 |= mb.z; }
#define PROC_WORD(W, RW) { \
    unsigned fr = ~RW; \
    while (fr) { \
        int bit = __ffs(fr) - 1; \
        PROC_ROW((W << 5) + bit); \
        fr = (~RW) & (0xFFFFFFFEu << bit); \
    } }
            PROC_WORD(0, r0) PROC_WORD(1, r1) PROC_WORD(2, r2) PROC_WORD(3, r3)
            PROC_WORD(4, r4) PROC_WORD(5, r5) PROC_WORD(6, r6)
#undef PROC_WORD
#undef PROC_ROW
            remw[0] = r0; remw[1] = r1; remw[2] = r2; remw[3] = r3;
            remw[4] = r4; remw[5] = r5; remw[6] = r6;
        }
    }
    __syncthreads();

    if (tid == 0) {
        int s2 = 0;
        for (int w = 0; w < 7; w++) {
            unsigned valid = (w < 6) ? 0xffffffffu : 0xffu;   // 200 = 6*32+8
            woff[w] = s2;
            s2 += __popc(~remw[w] & valid);
        }
        g_kcnt[bc] = s2;
    }
    __syncthreads();
    if (tid < KTOP) {
        int w = tid >> 5;
        bool keep = !((remw[w] >> (tid & 31)) & 1u);
        if (keep) {
            int pos = woff[w] + __popc(~remw[w] & ((1u << (tid & 31)) - 1u));
            g_ks[bc * KTOP + pos] = ss[tid];
            g_km[bc * KTOP + pos] = an[tid];
        }
    }
}

// ---------------- K4: per-image rank-merge + decode + emit -------------------
__global__ void k_out(const float* __restrict__ deltas,
                      const float* __restrict__ dbox,
                      float* __restrict__ out) {
    int b = blockIdx.x;
    int tid = threadIdx.x;                      // 1024 threads
    __shared__ float skey[NFG * KTOP];
    __shared__ int   san[NFG * KTOP];
    __shared__ int   scnt[NFG];
    __shared__ int   total;
    if (tid < NFG) scnt[tid] = g_kcnt[b * NFG + tid];
    for (int i = tid; i < NFG * KTOP; i += 1024) {
        skey[i] = g_ks[b * NFG * KTOP + i];
        san[i]  = g_km[b * NFG * KTOP + i];
    }
    if (tid == 0) {
        int t = 0;
        for (int c = 0; c < NFG; c++) t += g_kcnt[b * NFG + c];
        total = t < KTOP ? t : KTOP;
    }
    __syncthreads();
    for (int i = total + tid; i < KTOP; i += 1024) {
        ((float4*)out)[b * KTOP + i] = make_float4(0.f, 0.f, 0.f, 0.f);
        out[BATCH * KTOP * 4 + b * KTOP + i] = 0.f;
        out[BATCH * KTOP * 5 + b * KTOP + i] = 0.f;
    }
    for (int i = tid; i < NFG * KTOP; i += 1024) {
        int c = i / KTOP, p = i - c * KTOP;
        if (p < scnt[c]) {
            float k = skey[i];
            int rank = p;
#pragma unroll
            for (int c2 = 0; c2 < NFG; c2++) {
                if (c2 == c) continue;
                int lo = 0, hi = scnt[c2];
                while (lo < hi) {
                    int mid = (lo + hi) >> 1;
                    float v = skey[c2 * KTOP + mid];
                    bool prec = (v > k) || (v == k && c2 < c);
                    if (prec) lo = mid + 1; else hi = mid;
                }
                rank += lo;
            }
            if (rank < KTOP) {
                int a = san[i];
                float4 d  = ((const float4*)deltas)[(size_t)b * A_TOT + a];
                float4 db = ((const float4*)dbox)[a];
                float4 bx = decode_box(d, db);
                ((float4*)out)[b * KTOP + rank] = bx;
                out[BATCH * KTOP * 4 + b * KTOP + rank] = k;
                out[BATCH * KTOP * 5 + b * KTOP + rank] = (float)(c + 1);
            }
        }
    }
}

// -----------------------------------------------------------------------------
extern "C" void kernel_launch(void* const* d_in, const int* in_sizes, int n_in,
                              void* d_out, int out_size) {
    const float* logits = nullptr;
    const float* deltas = nullptr;
    const float* dbox   = nullptr;
    for (int i = 0; i < n_in; i++) {
        if      (in_sizes[i] == BATCH * A_TOT * 8) logits = (const float*)d_in[i];
        else if (in_sizes[i] == BATCH * A_TOT * 4) deltas = (const float*)d_in[i];
        else if (in_sizes[i] == A_TOT * 4)         dbox   = (const float*)d_in[i];
    }
    float* out = (float*)d_out;

    k_zero<<<(NBC * NBIN / 4 + 1023) / 1024, 1024>>>();
    k_prep<<<BATCH * 16, 256>>>(logits);
    k_sel<<<NBC, 256>>>();
    k_nms<<<NBC, 512>>>(logits, deltas, dbox);
    k_out<<<BATCH, 1024>>>(deltas, dbox, out);
}

// round 16
// speedup vs baseline: 1.2406x; 1.1514x over previous
#include <cuda_runtime.h>
#include <cstdint>

#define A_TOT 49056
#define AHALF 24528              // key-pair words per (b,c) plane
#define BATCH 32
#define NFG 7
#define KTOP 200
#define NBC 224
#define NCHUNK 767               // ceil(AHALF/32) chunks of 32 words (64 anchors)
#define NCHUNKP 768
#define CANDMAX 4096
#define SORTMAX 2048
#define NMS_THR_F 0.45f
#define LOW_SCORE_F 0.01f

// ---------------- scratch (device globals) -----------------------------------
__device__ unsigned g_k16[(size_t)NBC * AHALF];        // packed (key16 lo | key16 hi)
__device__ unsigned short g_wmax[NBC * NCHUNKP];       // per-chunk max key16
__device__ float g_ks[NBC * KTOP];                     // kept scores (sorted desc)
__device__ int   g_km[NBC * KTOP];                     // kept anchors
__device__ int   g_kcnt[NBC];

// ---- exact softmax (candidates only; bit-exact final ordering) --------------
__device__ __forceinline__ void softmax8(const float4 l0, const float4 l1, float* fg7) {
    float x[8] = {l0.x, l0.y, l0.z, l0.w, l1.x, l1.y, l1.z, l1.w};
    float mx = x[0];
#pragma unroll
    for (int i = 1; i < 8; i++) mx = fmaxf(mx, x[i]);
    float e[8]; float sum = 0.f;
#pragma unroll
    for (int i = 0; i < 8; i++) { e[i] = expf(x[i] - mx); sum += e[i]; }
    float inv = 1.0f / sum;
#pragma unroll
    for (int c = 0; c < NFG; c++) fg7[c] = e[c + 1] * inv;
}

// ---- polynomial exp2: no MUFU, rel err <= ~1e-5 -----------------------------
__device__ __forceinline__ float fexp2(float t) {
    t = fminf(fmaxf(t, -60.f), 60.f);
    float r = rintf(t);
    float f = t - r;                                   // [-0.5, 0.5]
    float u = f * 0.6931471805599453f;
    float p = 1.0f + u * (1.0f + u * (0.5f + u * (0.16666667f
              + u * (0.041666667f + u * 0.0083333333f))));
    return p * __int_as_float(((int)r + 127) << 23);
}
__device__ __forceinline__ void softmax8_fast(const float4 l0, const float4 l1, float* fg7) {
    float x[8] = {l0.x, l0.y, l0.z, l0.w, l1.x, l1.y, l1.z, l1.w};
    float e[8]; float sum = 0.f;
#pragma unroll
    for (int i = 0; i < 8; i++) { e[i] = fexp2(x[i] * 1.4426950408889634f); sum += e[i]; }
    float inv = __fdividef(1.0f, sum);
#pragma unroll
    for (int c = 0; c < NFG; c++) fg7[c] = e[c + 1] * inv;
}

__device__ __forceinline__ float4 decode_box(float4 d, float4 db) {
    float w  = db.z - db.x,  h  = db.w - db.y;
    float cx = db.x + 0.5f * w, cy = db.y + 0.5f * h;
    float pcx = d.x / 10.0f * w + cx;
    float pcy = d.y / 10.0f * h + cy;
    float pw  = expf(d.z / 5.0f) * w;
    float ph  = expf(d.w / 5.0f) * h;
    return make_float4(
        fminf(fmaxf(pcx - 0.5f * pw, 0.f), 1.f),
        fminf(fmaxf(pcy - 0.5f * ph, 0.f), 1.f),
        fminf(fmaxf(pcx + 0.5f * pw, 0.f), 1.f),
        fminf(fmaxf(pcy + 0.5f * ph, 0.f), 1.f));
}

// ---------------- K1: fast softmax -> keys + chunk maxima (NO histogram) -----
__global__ __launch_bounds__(512) void k_prep(const float* __restrict__ logits) {
    int b = blockIdx.x >> 2;                   // 4 blocks per image, 512 threads
    int q = blockIdx.x & 3;
    int tid = threadIdx.x;
    int lane = tid & 31, wrp = tid >> 5;
    unsigned halfmask = (lane < 16) ? 0x0000FFFFu : 0xFFFF0000u;

#pragma unroll 1
    for (int k = 0; k < 6; k++) {
        int base = q * 6144 + k * 1024 + wrp * 64;   // warp covers 64 words (2 chunks)
        int w0 = base + lane * 2;                    // this thread: words w0, w0+1 (4 anchors)
        bool act = w0 < AHALF;                       // AHALF even, w0 even => w0+1 valid too
        float f0[NFG], f1[NFG], f2[NFG], f3[NFG];
        if (act) {
            const float4* lp = (const float4*)logits + ((size_t)b * A_TOT + 2 * w0) * 2;
            softmax8_fast(lp[0], lp[1], f0);
            softmax8_fast(lp[2], lp[3], f1);
            softmax8_fast(lp[4], lp[5], f2);
            softmax8_fast(lp[6], lp[7], f3);
        }
        int cid = (base >> 5) + (lane >> 4);         // chunk id owned by this half-warp
#pragma unroll
        for (int c = 0; c < NFG; c++) {
            unsigned v16 = 0;
            if (act) {
                unsigned pA = (__float_as_uint(f0[c]) >> 16) | (__float_as_uint(f1[c]) & 0xFFFF0000u);
                unsigned pB = (__float_as_uint(f2[c]) >> 16) | (__float_as_uint(f3[c]) & 0xFFFF0000u);
                unsigned* pl = g_k16 + (size_t)(b * NFG + c) * AHALF;
                *(unsigned long long*)(pl + w0) =
                    (unsigned long long)pA | ((unsigned long long)pB << 32);
                unsigned mA = max(pA & 0xFFFFu, pA >> 16);
                unsigned mB = max(pB & 0xFFFFu, pB >> 16);
                v16 = max(mA, mB);
            }
            unsigned wm = __reduce_max_sync(halfmask, v16);
            if ((lane & 15) == 0)
                g_wmax[(b * NFG + c) * NCHUNKP + cid] = (unsigned short)wm;
        }
    }
}

// ---------------- K2: fused select + exact sort + NMS + compact --------------
// Threshold chain (all on approx keys, consistent):
//   m200 := 200th-largest chunk max  =>  >=200 chunks have an element >= m200
//   => >=200 elements >= floor(bin(m200)) = B<<5.  Fine threshold t at key16
//   resolution from exact band counts; thr = t-2 ulps covers approx error.
__global__ __launch_bounds__(256) void k_selnms(const float* __restrict__ logits,
                                                const float* __restrict__ deltas,
                                                const float* __restrict__ dbox) {
    int bc = blockIdx.x;
    int b = bc / NFG, c = bc % NFG;
    int tid = threadIdx.x;                      // 256 threads
    int lane = tid & 31, wid = tid >> 5;

    __shared__ unsigned long long sortbuf[SORTMAX];   // 16 KB
    __shared__ union U {
        unsigned histA[2048];                         // Phase A: chunk-max bins (8 KB)
        int cand[CANDMAX];                            // Phase C: candidates (16 KB)
        struct {
            uint4 mask4[KTOP * 2];                    // 6.4 KB, 16B-aligned
            float x0[KTOP], y0[KTOP], x1[KTOP], y1[KTOP], ar[KTOP], ss[KTOP];
            int an[KTOP];
        } nb;                                         // 12 KB
    } u;
    __shared__ int hits[NCHUNKP];                     // 3 KB
    __shared__ int csum[256];
    __shared__ int suf[257];
    __shared__ int subh[64];
    __shared__ int sh_B, sh_thr, hcnt, ccnt, above2;
    __shared__ unsigned remw[7];
    __shared__ int woff[8];

    // --- Phase A: coarse bin B from chunk maxima -----------------------------
    for (int i = tid; i < 2048; i += 256) u.histA[i] = 0;
    if (tid < 64) subh[tid] = 0;
    if (tid == 0) { sh_B = 0; hcnt = 0; ccnt = 0; above2 = 0; }
    __syncthreads();
    const unsigned short* wmax = g_wmax + bc * NCHUNKP;
#pragma unroll
    for (int it = 0; it < 3; it++) {
        int cid = tid + it * 256;
        if (cid < NCHUNK) atomicAdd(&u.histA[(unsigned)wmax[cid] >> 5], 1u);
    }
    __syncthreads();
    unsigned loc[8]; int s = 0; int base8 = tid * 8;
#pragma unroll
    for (int i = 0; i < 8; i++) { loc[i] = u.histA[base8 + i]; s += (int)loc[i]; }
    csum[tid] = s;
    __syncthreads();
    if (tid == 0) {
        int acc = 0; suf[256] = 0;
        for (int t = 255; t >= 0; t--) { acc += csum[t]; suf[t] = acc; }
    }
    __syncthreads();
    int above0 = suf[tid + 1];
    if (above0 < KTOP && above0 + s >= KTOP) {
        int cum = above0;
        for (int i = 7; i >= 0; i--) {
            cum += (int)loc[i];
            if (cum >= KTOP) { sh_B = base8 + i; break; }
        }
    }
    __syncthreads();
    int B = sh_B;
    int ht = (B << 5) - 2; if (ht < 0) ht = 0;
    unsigned hthr = (unsigned)ht;

    // --- Phase B: chunks that can contain candidates -------------------------
#pragma unroll
    for (int it = 0; it < 3; it++) {
        int cid = tid + it * 256;
        bool pass = (cid < NCHUNK) && ((unsigned)wmax[cid] >= hthr);
        unsigned m = __ballot_sync(0xffffffffu, pass);
        if (m) {
            int bse = 0;
            if (lane == __ffs(m) - 1) bse = atomicAdd(&hcnt, __popc(m));
            bse = __shfl_sync(0xffffffffu, bse, __ffs(m) - 1);
            if (pass) hits[bse + __popc(m & ((1u << lane) - 1u))] = cid;
        }
    }
    __syncthreads();
    int nh = hcnt;
    const unsigned* plane = g_k16 + (size_t)bc * AHALF;

    // --- Phase C1: key16 sub-histogram over band [B<<5, (B+2)<<5) ------------
    unsigned lo = (unsigned)(B << 5), hi = lo + 64;
    for (int hh = wid; hh < nh; hh += 8) {
        int w = hits[hh] * 32 + lane;
        int a2 = 0;
        if (w < AHALF) {
            unsigned v = plane[w];
            unsigned k0 = v & 0xffffu, k1 = v >> 16;
            if (k0 >= hi) a2++;
            else if (k0 >= lo) atomicAdd(&subh[k0 - lo], 1);
            if (k1 >= hi) a2++;
            else if (k1 >= lo) atomicAdd(&subh[k1 - lo], 1);
        }
        int wa = __reduce_add_sync(0xffffffffu, a2);
        if (lane == 0 && wa) atomicAdd(&above2, wa);
    }
    __syncthreads();
    if (tid == 0) {
        int t = (int)hi;                          // explicit fallback: 200th above band
        if (above2 < KTOP) {
            int acc = above2;
            for (int s2 = 63; s2 >= 0; s2--) {
                acc += subh[s2];
                if (acc >= KTOP) { t = (int)lo + s2; break; }
            }
        }
        t -= 2;                                   // 2-ulp superset margin
        sh_thr = t > 0 ? t : 0;
    }
    __syncthreads();
    unsigned thr = (unsigned)sh_thr;

    // --- Phase C2: compact candidates (key16 >= thr) into smem ---------------
    for (int hh = wid; hh < nh; hh += 8) {
        int w = hits[hh] * 32 + lane;
        unsigned v = (w < AHALF) ? plane[w] : 0u;
        bool p0 = (w < AHALF) && ((v & 0xffffu) >= thr);
        bool p1 = (w < AHALF) && ((v >> 16) >= thr);
        unsigned m0 = __ballot_sync(0xffffffffu, p0);
        unsigned m1 = __ballot_sync(0xffffffffu, p1);
        int c0 = __popc(m0), c1 = __popc(m1);
        if (c0 + c1) {
            int bse = 0;
            if (lane == 0) bse = atomicAdd(&ccnt, c0 + c1);
            bse = __shfl_sync(0xffffffffu, bse, 0);
            unsigned below = (1u << lane) - 1u;
            if (p0) { int p = bse + __popc(m0 & below);      if (p < CANDMAX) u.cand[p] = 2 * w; }
            if (p1) { int p = bse + c0 + __popc(m1 & below); if (p < CANDMAX) u.cand[p] = 2 * w + 1; }
        }
    }
    __syncthreads();
    int n = ccnt; if (n > SORTMAX) n = SORTMAX;

    // --- exact composite keys -> sortbuf -------------------------------------
    for (int i = tid; i < n; i += 256) {
        int a = u.cand[i];
        const float4* lp = (const float4*)logits + ((size_t)b * A_TOT + a) * 2;
        float fg[NFG];
        softmax8(lp[0], lp[1], fg);               // EXACT for final ordering
        sortbuf[i] = ((unsigned long long)__float_as_uint(fg[c]) << 32)
                   | (unsigned)(A_TOT - a);
    }
    int npad = 256; while (npad < n) npad <<= 1;
    for (int i = n + tid; i < npad; i += 256) sortbuf[i] = 0ULL;
    __syncthreads();

    // --- bitonic sort (typically npad == 256/512) ----------------------------
    for (int k = 2; k <= npad; k <<= 1)
        for (int j = k >> 1; j > 0; j >>= 1) {
            for (int t = tid; t < npad; t += 256) {
                int l = t ^ j;
                if (l > t) {
                    bool desc = ((t & k) == 0);
                    unsigned long long va = sortbuf[t], vb = sortbuf[l];
                    if (desc ? (va < vb) : (va > vb)) { sortbuf[t] = vb; sortbuf[l] = va; }
                }
            }
            __syncthreads();
        }
    // u.cand dead from here -> union switch to u.nb

    unsigned* mask = (unsigned*)u.nb.mask4;
    for (int i = tid; i < KTOP * 8; i += 256) mask[i] = 0;
    if (tid < KTOP) {
        unsigned long long vv = sortbuf[tid];
        unsigned key = (unsigned)(vv >> 32);
        int a = A_TOT - (int)(vv & 0xffffffffu);
        if (vv == 0ULL) a = 0;                    // padding: score 0, never kept
        float4 d  = ((const float4*)deltas)[(size_t)b * A_TOT + a];
        float4 db = ((const float4*)dbox)[a];
        float4 bx = decode_box(d, db);
        u.nb.x0[tid] = bx.x; u.nb.y0[tid] = bx.y; u.nb.x1[tid] = bx.z; u.nb.y1[tid] = bx.w;
        u.nb.ar[tid] = (bx.z - bx.x) * (bx.w - bx.y);
        u.nb.ss[tid] = __uint_as_float(key); u.nb.an[tid] = a;
    }
    __syncthreads();

    for (int p = tid; p < KTOP * KTOP; p += 256) {
        int i = p / KTOP, j = p - i * KTOP;
        if (j > i) {
            float xl = fmaxf(u.nb.x0[i], u.nb.x0[j]);
            float yt = fmaxf(u.nb.y0[i], u.nb.y0[j]);
            float xr = fminf(u.nb.x1[i], u.nb.x1[j]);
            float yb = fminf(u.nb.y1[i], u.nb.y1[j]);
            float inter = fmaxf(xr - xl, 0.f) * fmaxf(yb - yt, 0.f);
            float iou = inter / (u.nb.ar[i] + u.nb.ar[j] - inter);  // NaN -> false
            if (iou > NMS_THR_F) atomicOr(&mask[i * 8 + (j >> 5)], 1u << (j & 31));
        }
    }
    __syncthreads();

    // --- greedy: warp-0 ballots init, then single-lane register scan ---------
    if (tid < 32) {
        unsigned bw[7];
#pragma unroll
        for (int w = 0; w < 7; w++) {
            int jj = w * 32 + lane;
            bool bad = (jj >= KTOP) || !(u.nb.ss[jj] > LOW_SCORE_F);
            bw[w] = __ballot_sync(0xffffffffu, bad);
        }
        if (lane == 0) {
            unsigned r0 = bw[0], r1 = bw[1], r2 = bw[2], r3 = bw[3],
                     r4 = bw[4], r5 = bw[5], r6 = bw[6];
#define PROC_ROW(ib) { \
    uint4 ma = u.nb.mask4[(ib) * 2], mb = u.nb.mask4[(ib) * 2 + 1]; \
    r0 |= ma.x; r1 |= ma.y; r2 |= ma.z; r3 |= ma.w; \
    r4 |= mb.x; r5 |= mb.y; r6 |= mb.z; }
#define PROC_WORD(W, RW) { \
    unsigned fr = ~RW; \
    while (fr) { \
        int bit = __ffs(fr) - 1; \
        PROC_ROW((W << 5) + bit); \
        fr = (~RW) & (0xFFFFFFFEu << bit); \
    } }
            PROC_WORD(0, r0) PROC_WORD(1, r1) PROC_WORD(2, r2) PROC_WORD(3, r3)
            PROC_WORD(4, r4) PROC_WORD(5, r5) PROC_WORD(6, r6)
#undef PROC_WORD
#undef PROC_ROW
            remw[0] = r0; remw[1] = r1; remw[2] = r2; remw[3] = r3;
            remw[4] = r4; remw[5] = r5; remw[6] = r6;
        }
    }
    __syncthreads();

    if (tid == 0) {
        int s2 = 0;
        for (int w = 0; w < 7; w++) {
            unsigned valid = (w < 6) ? 0xffffffffu : 0xffu;   // 200 = 6*32+8
            woff[w] = s2;
            s2 += __popc(~remw[w] & valid);
        }
        g_kcnt[bc] = s2;
    }
    __syncthreads();
    if (tid < KTOP) {
        int w = tid >> 5;
        bool keep = !((remw[w] >> (tid & 31)) & 1u);
        if (keep) {
            int pos = woff[w] + __popc(~remw[w] & ((1u << (tid & 31)) - 1u));
            g_ks[bc * KTOP + pos] = u.nb.ss[tid];
            g_km[bc * KTOP + pos] = u.nb.an[tid];
        }
    }
}

// ---------------- K3: per-image rank-merge + decode + emit -------------------
__global__ void k_out(const float* __restrict__ deltas,
                      const float* __restrict__ dbox,
                      float* __restrict__ out) {
    int b = blockIdx.x;
    int tid = threadIdx.x;                      // 1024 threads
    __shared__ float skey[NFG * KTOP];
    __shared__ int   san[NFG * KTOP];
    __shared__ int   scnt[NFG];
    __shared__ int   total;
    if (tid < NFG) scnt[tid] = g_kcnt[b * NFG + tid];
    for (int i = tid; i < NFG * KTOP; i += 1024) {
        skey[i] = g_ks[b * NFG * KTOP + i];
        san[i]  = g_km[b * NFG * KTOP + i];
    }
    if (tid == 0) {
        int t = 0;
        for (int c = 0; c < NFG; c++) t += g_kcnt[b * NFG + c];
        total = t < KTOP ? t : KTOP;
    }
    __syncthreads();
    for (int i = total + tid; i < KTOP; i += 1024) {
        ((float4*)out)[b * KTOP + i] = make_float4(0.f, 0.f, 0.f, 0.f);
        out[BATCH * KTOP * 4 + b * KTOP + i] = 0.f;
        out[BATCH * KTOP * 5 + b * KTOP + i] = 0.f;
    }
    for (int i = tid; i < NFG * KTOP; i += 1024) {
        int c = i / KTOP, p = i - c * KTOP;
        if (p < scnt[c]) {
            float k = skey[i];
            int rank = p;
#pragma unroll
            for (int c2 = 0; c2 < NFG; c2++) {
                if (c2 == c) continue;
                int lo = 0, hi = scnt[c2];
                while (lo < hi) {
                    int mid = (lo + hi) >> 1;
                    float v = skey[c2 * KTOP + mid];
                    bool prec = (v > k) || (v == k && c2 < c);
                    if (prec) lo = mid + 1; else hi = mid;
                }
                rank += lo;
            }
            if (rank < KTOP) {
                int a = san[i];
                float4 d  = ((const float4*)deltas)[(size_t)b * A_TOT + a];
                float4 db = ((const float4*)dbox)[a];
                float4 bx = decode_box(d, db);
                ((float4*)out)[b * KTOP + rank] = bx;
                out[BATCH * KTOP * 4 + b * KTOP + rank] = k;
                out[BATCH * KTOP * 5 + b * KTOP + rank] = (float)(c + 1);
            }
        }
    }
}

// -----------------------------------------------------------------------------
extern "C" void kernel_launch(void* const* d_in, const int* in_sizes, int n_in,
                              void* d_out, int out_size) {
    const float* logits = nullptr;
    const float* deltas = nullptr;
    const float* dbox   = nullptr;
    for (int i = 0; i < n_in; i++) {
        if      (in_sizes[i] == BATCH * A_TOT * 8) logits = (const float*)d_in[i];
        else if (in_sizes[i] == BATCH * A_TOT * 4) deltas = (const float*)d_in[i];
        else if (in_sizes[i] == A_TOT * 4)         dbox   = (const float*)d_in[i];
    }
    float* out = (float*)d_out;

    k_prep<<<BATCH * 4, 512>>>(logits);
    k_selnms<<<NBC, 256>>>(logits, deltas, dbox);
    k_out<<<BATCH, 1024>>>(deltas, dbox, out);
}